// round 7
// baseline (speedup 1.0000x reference)
#include <cuda_runtime.h>
#include <math.h>

// Problem constants
#define BQ    8
#define TT    1024
#define EMB   1024
#define NH    16
#define DH    64
#define NTOK  (BQ*TT)      // 8192
#define BHD   (BQ*NH)      // 128 (batch*heads)

// -------- scratch (static device arrays: no allocation APIs allowed) --------
__device__ float g_q [BHD*TT*DH];   // [b,h,t,d]
__device__ float g_k [BHD*TT*DH];
__device__ float g_v [BHD*TT*DH];
__device__ float g_ao[NTOK*EMB];    // attention output [b*t, h*d]

// ============================================================================
// SGEMM: C[m][n] = sum_k A[m][k]*B[n][k] + bias[n]
// M=8192, N=1024, K=1024. Block tile 128x128, k-step 16, 256 thr, 8x8 microtile.
// mode 0: write row-major to C (out projection / final output)
// mode 1: scatter into [b,h,t,d] layout (QKV projection)
// ============================================================================
#define GTK  16
#define ASTR 132   // smem row stride (floats), %4==0 for float4, bank-skewed

__global__ __launch_bounds__(256, 2)
void sgemm_kernel(const float* __restrict__ A, const float* __restrict__ B,
                  const float* __restrict__ bias, float* __restrict__ C, int mode)
{
    __shared__ float As[GTK][ASTR];
    __shared__ float Bs[GTK][ASTR];

    const int tid = threadIdx.x;
    const int tx  = tid & 15;          // 0..15 -> 8 cols each
    const int ty  = tid >> 4;          // 0..15 -> 8 rows each
    const int m0  = blockIdx.y * 128;
    const int n0  = blockIdx.x * 128;

    const int lr = tid >> 2;           // 0..63 (load row)
    const int kv = (tid & 3) * 4;      // 0,4,8,12 (load k-vector)

    float acc[8][8];
#pragma unroll
    for (int i = 0; i < 8; i++)
#pragma unroll
        for (int j = 0; j < 8; j++) acc[i][j] = 0.f;

    for (int kb = 0; kb < 1024; kb += GTK) {
        // load A,B tiles transposed into smem
#pragma unroll
        for (int h = 0; h < 2; h++) {
            int r = lr + 64*h;
            float4 a = *(const float4*)(A + (size_t)(m0 + r)*1024 + kb + kv);
            As[kv+0][r] = a.x; As[kv+1][r] = a.y; As[kv+2][r] = a.z; As[kv+3][r] = a.w;
            float4 b = *(const float4*)(B + (size_t)(n0 + r)*1024 + kb + kv);
            Bs[kv+0][r] = b.x; Bs[kv+1][r] = b.y; Bs[kv+2][r] = b.z; Bs[kv+3][r] = b.w;
        }
        __syncthreads();
#pragma unroll
        for (int k = 0; k < GTK; k++) {
            float af[8], bf[8];
            *(float4*)&af[0] = *(const float4*)&As[k][8*ty];
            *(float4*)&af[4] = *(const float4*)&As[k][8*ty + 4];
            *(float4*)&bf[0] = *(const float4*)&Bs[k][8*tx];
            *(float4*)&bf[4] = *(const float4*)&Bs[k][8*tx + 4];
#pragma unroll
            for (int i = 0; i < 8; i++)
#pragma unroll
                for (int j = 0; j < 8; j++)
                    acc[i][j] += af[i] * bf[j];
        }
        __syncthreads();
    }

    float bv[8];
#pragma unroll
    for (int j = 0; j < 8; j++) bv[j] = bias[n0 + 8*tx + j];

    if (mode == 0) {
#pragma unroll
        for (int i = 0; i < 8; i++) {
            int m = m0 + 8*ty + i;
#pragma unroll
            for (int jj = 0; jj < 2; jj++) {
                float4 v;
                v.x = acc[i][4*jj+0] + bv[4*jj+0];
                v.y = acc[i][4*jj+1] + bv[4*jj+1];
                v.z = acc[i][4*jj+2] + bv[4*jj+2];
                v.w = acc[i][4*jj+3] + bv[4*jj+3];
                *(float4*)&C[(size_t)m*1024 + n0 + 8*tx + 4*jj] = v;
            }
        }
    } else {
#pragma unroll
        for (int i = 0; i < 8; i++) {
            int m = m0 + 8*ty + i;
            int b = m >> 10, t = m & 1023;
#pragma unroll
            for (int jj = 0; jj < 2; jj++) {
                int n = n0 + 8*tx + 4*jj;
                int h = n >> 6, d = n & 63;
                float4 v;
                v.x = acc[i][4*jj+0] + bv[4*jj+0];
                v.y = acc[i][4*jj+1] + bv[4*jj+1];
                v.z = acc[i][4*jj+2] + bv[4*jj+2];
                v.w = acc[i][4*jj+3] + bv[4*jj+3];
                *(float4*)&C[(size_t)(((b*NH + h)*TT + t))*DH + d] = v;
            }
        }
    }
}

// ============================================================================
// Flash attention: per block (bh, 64-query tile), loop over 16 key tiles of 64.
// 128 threads: ty 0..7 (8 rows each), tx 0..15 (4 cols each).
// Online softmax; attn_mask + key_padding_mask folded into smem addend tile.
// ============================================================================
#define FSTR 68                     // smem row stride, %4==0, bank-skewed
#define FSZ  (64*FSTR)              // floats per tile
#define FLASH_SMEM (5*FSZ*4)        // Qt,Kt,Vs,Pt,Ms = 87040 B

__global__ __launch_bounds__(128, 2)
void flash_kernel(const float* __restrict__ amask,
                  const unsigned char* __restrict__ kpm)
{
    extern __shared__ float smem[];
    float* Qt = smem;               // [d][m]
    float* Kt = Qt + FSZ;           // [d][n]
    float* Vs = Kt + FSZ;           // [n][d]
    float* Pt = Vs + FSZ;           // [n][m]
    float* Ms = Pt + FSZ;           // [m][n] mask addend

    const int tid = threadIdx.x;
    const int tx  = tid & 15;       // 0..15
    const int ty  = tid >> 4;       // 0..7
    const int bh  = blockIdx.x;     // 0..127
    const int b   = bh >> 4;
    const int m0  = blockIdx.y * 64;

    const float* Qg = g_q + ((size_t)bh*TT + m0)*DH;
    const float* Kg = g_k + (size_t)bh*TT*DH;
    const float* Vg = g_v + (size_t)bh*TT*DH;

    // Load Q tile transposed (once per block)
#pragma unroll
    for (int p = 0; p < 8; p++) {
        int lin = tid + p*128;        // 0..1023
        int m   = lin >> 4;           // 0..63
        int dv  = (lin & 15) * 4;
        float4 q4 = *(const float4*)(Qg + m*DH + dv);
        Qt[(dv+0)*FSTR + m] = q4.x;
        Qt[(dv+1)*FSTR + m] = q4.y;
        Qt[(dv+2)*FSTR + m] = q4.z;
        Qt[(dv+3)*FSTR + m] = q4.w;
    }

    float oacc[8][4];
    float mrow[8], lrow[8];
#pragma unroll
    for (int i = 0; i < 8; i++) {
        mrow[i] = -1e30f; lrow[i] = 0.f;
#pragma unroll
        for (int j = 0; j < 4; j++) oacc[i][j] = 0.f;
    }

    const float scale = 0.125f;      // 1/sqrt(64)

    for (int n0k = 0; n0k < TT; n0k += 64) {
        __syncthreads();  // prior iteration's reads of Kt/Vs/Pt/Ms are done

        // load K (transposed), V (direct), mask addend tile
#pragma unroll
        for (int p = 0; p < 8; p++) {
            int lin = tid + p*128;
            int r   = lin >> 4;          // 0..63
            int dv  = (lin & 15) * 4;
            float4 k4 = *(const float4*)(Kg + (size_t)(n0k + r)*DH + dv);
            Kt[(dv+0)*FSTR + r] = k4.x;
            Kt[(dv+1)*FSTR + r] = k4.y;
            Kt[(dv+2)*FSTR + r] = k4.z;
            Kt[(dv+3)*FSTR + r] = k4.w;
            float4 v4 = *(const float4*)(Vg + (size_t)(n0k + r)*DH + dv);
            *(float4*)&Vs[r*FSTR + dv] = v4;
            // mask: row r is a QUERY row here; cols dv..dv+3 are key positions
            float4 a4 = *(const float4*)(amask + (size_t)(m0 + r)*TT + n0k + dv);
            float p0 = kpm[b*TT + n0k + dv + 0] ? -1e30f : 0.f;
            float p1 = kpm[b*TT + n0k + dv + 1] ? -1e30f : 0.f;
            float p2 = kpm[b*TT + n0k + dv + 2] ? -1e30f : 0.f;
            float p3 = kpm[b*TT + n0k + dv + 3] ? -1e30f : 0.f;
            Ms[r*FSTR + dv + 0] = a4.x + p0;
            Ms[r*FSTR + dv + 1] = a4.y + p1;
            Ms[r*FSTR + dv + 2] = a4.z + p2;
            Ms[r*FSTR + dv + 3] = a4.w + p3;
        }
        __syncthreads();

        // S = Q @ K^T  (8x4 frag per thread)
        float s[8][4];
#pragma unroll
        for (int i = 0; i < 8; i++)
#pragma unroll
            for (int j = 0; j < 4; j++) s[i][j] = 0.f;

#pragma unroll 16
        for (int d = 0; d < 64; d++) {
            float af[8], bf[4];
            *(float4*)&af[0] = *(const float4*)&Qt[d*FSTR + 8*ty];
            *(float4*)&af[4] = *(const float4*)&Qt[d*FSTR + 8*ty + 4];
            *(float4*)&bf[0] = *(const float4*)&Kt[d*FSTR + 4*tx];
#pragma unroll
            for (int i = 0; i < 8; i++)
#pragma unroll
                for (int j = 0; j < 4; j++)
                    s[i][j] += af[i] * bf[j];
        }

        // scale + mask, online softmax
        float p[8][4];
#pragma unroll
        for (int i = 0; i < 8; i++) {
            float mx = -1e30f;
#pragma unroll
            for (int j = 0; j < 4; j++) {
                s[i][j] = s[i][j]*scale + Ms[(8*ty + i)*FSTR + 4*tx + j];
                mx = fmaxf(mx, s[i][j]);
            }
#pragma unroll
            for (int off = 1; off < 16; off <<= 1)
                mx = fmaxf(mx, __shfl_xor_sync(0xffffffffu, mx, off));
            float mnew  = fmaxf(mrow[i], mx);
            float alpha = __expf(mrow[i] - mnew);
            mrow[i] = mnew;
            float rs = 0.f;
#pragma unroll
            for (int j = 0; j < 4; j++) {
                p[i][j] = __expf(s[i][j] - mnew);
                rs += p[i][j];
            }
#pragma unroll
            for (int off = 1; off < 16; off <<= 1)
                rs += __shfl_xor_sync(0xffffffffu, rs, off);
            lrow[i] = lrow[i]*alpha + rs;
#pragma unroll
            for (int j = 0; j < 4; j++) oacc[i][j] *= alpha;
        }

        // stash P transposed for the PV GEMM
#pragma unroll
        for (int i = 0; i < 8; i++)
#pragma unroll
            for (int j = 0; j < 4; j++)
                Pt[(4*tx + j)*FSTR + 8*ty + i] = p[i][j];
        __syncthreads();

        // O += P @ V
#pragma unroll 16
        for (int n = 0; n < 64; n++) {
            float af[8], bf[4];
            *(float4*)&af[0] = *(const float4*)&Pt[n*FSTR + 8*ty];
            *(float4*)&af[4] = *(const float4*)&Pt[n*FSTR + 8*ty + 4];
            *(float4*)&bf[0] = *(const float4*)&Vs[n*FSTR + 4*tx];
#pragma unroll
            for (int i = 0; i < 8; i++)
#pragma unroll
                for (int j = 0; j < 4; j++)
                    oacc[i][j] += af[i] * bf[j];
        }
    }

    // normalize & write [b, t, h*64 + d]
    const int hh = bh & 15;
#pragma unroll
    for (int i = 0; i < 8; i++) {
        int t = m0 + 8*ty + i;
        float inv = 1.0f / lrow[i];
        float4 v;
        v.x = oacc[i][0]*inv; v.y = oacc[i][1]*inv;
        v.z = oacc[i][2]*inv; v.w = oacc[i][3]*inv;
        *(float4*)&g_ao[(size_t)(b*TT + t)*EMB + hh*64 + 4*tx] = v;
    }
}

// ============================================================================
extern "C" void kernel_launch(void* const* d_in, const int* in_sizes, int n_in,
                              void* d_out, int out_size)
{
    (void)in_sizes; (void)n_in; (void)out_size;
    const float*         query = (const float*)d_in[0];
    const float*         key   = (const float*)d_in[1];
    const float*         value = (const float*)d_in[2];
    const unsigned char* kpm   = (const unsigned char*)d_in[3];
    const float*         amask = (const float*)d_in[4];
    const float*         win   = (const float*)d_in[5];
    const float*         bin   = (const float*)d_in[6];
    const float*         wout  = (const float*)d_in[7];
    const float*         bout  = (const float*)d_in[8];
    float*               out   = (float*)d_out;

    float *pq, *pk, *pv, *pao;
    cudaGetSymbolAddress((void**)&pq,  g_q);
    cudaGetSymbolAddress((void**)&pk,  g_k);
    cudaGetSymbolAddress((void**)&pv,  g_v);
    cudaGetSymbolAddress((void**)&pao, g_ao);

    dim3 gg(EMB/128, NTOK/128);   // (8, 64)

    // Q/K/V projections (scatter into [b,h,t,d])
    sgemm_kernel<<<gg, 256>>>(query, win,               bin,        pq, 1);
    sgemm_kernel<<<gg, 256>>>(key,   win +   1024*1024, bin + 1024, pk, 1);
    sgemm_kernel<<<gg, 256>>>(value, win + 2*1024*1024, bin + 2048, pv, 1);

    // Flash attention
    cudaFuncSetAttribute(flash_kernel,
                         cudaFuncAttributeMaxDynamicSharedMemorySize, FLASH_SMEM);
    flash_kernel<<<dim3(BHD, TT/64), 128, FLASH_SMEM>>>(amask, kpm);

    // Output projection -> d_out
    sgemm_kernel<<<gg, 256>>>(pao, wout, bout, out, 0);
}

// round 8
// speedup vs baseline: 2.6315x; 2.6315x over previous
#include <cuda_runtime.h>
#include <math.h>

// Problem constants
#define BQ    8
#define TT    1024
#define EMB   1024
#define NH    16
#define DH    64
#define NTOK  (BQ*TT)      // 8192
#define BHD   (BQ*NH)      // 128

#define LOG2E 1.4426950408889634f

// -------- scratch (static device arrays: no allocation APIs allowed) --------
__device__ float g_q [BHD*TT*DH];   // [b,h,t,d]
__device__ float g_k [BHD*TT*DH];
__device__ float g_v [BHD*TT*DH];
__device__ float g_ao[NTOK*EMB];    // attention output [b*t, h*d]

// ---------------------------------------------------------------------------
// helpers
// ---------------------------------------------------------------------------
__device__ __forceinline__ unsigned f2tf(float x) {
    unsigned u;
    asm("cvt.rna.tf32.f32 %0, %1;" : "=r"(u) : "f"(x));
    return u;
}
__device__ __forceinline__ float tff(float x) { return __uint_as_float(f2tf(x)); }

__device__ __forceinline__ void mma8(float* d, const unsigned* a, unsigned b0, unsigned b1) {
    asm volatile(
        "mma.sync.aligned.m16n8k8.row.col.f32.tf32.tf32.f32 "
        "{%0,%1,%2,%3}, {%4,%5,%6,%7}, {%8,%9}, {%0,%1,%2,%3};\n"
        : "+f"(d[0]), "+f"(d[1]), "+f"(d[2]), "+f"(d[3])
        : "r"(a[0]), "r"(a[1]), "r"(a[2]), "r"(a[3]), "r"(b0), "r"(b1));
}

// FMA-only exp2 (no MUFU). y <= 0 expected; clamped below -126 -> ~0.
__device__ __forceinline__ float exp2_fast(float y) {
    y = fmaxf(y, -126.0f);
    float r  = y + 12582912.0f;                 // round-to-nearest int
    int   n  = __float_as_int(r) - 0x4B400000;  // integer part
    float f  = y - (r - 12582912.0f);           // frac in [-0.5, 0.5]
    float p  =            1.3333558146428443e-3f;
    p = fmaf(p, f,        9.6181291076284771e-3f);
    p = fmaf(p, f,        5.5504108664821580e-2f);
    p = fmaf(p, f,        2.4022650695910072e-1f);
    p = fmaf(p, f,        6.9314718055994531e-1f);
    p = fmaf(p, f,        1.0f);
    return p * __int_as_float((n + 127) << 23);
}

// ---------------------------------------------------------------------------
// tf32 GEMM: C[m][n] = sum_k A[m][k]*B[n][k] + bias[n]
// M=8192 N=1024 K=1024. 128x128 tile, BK=32, 256 thr (8 warps, 4x2 warp grid,
// warp tile 32m x 64n, mma m16n8k8). Smem stride 36 -> conflict-free frags.
// mode 0: row-major C ; mode 1: scatter into [b,h,t,d]
// ---------------------------------------------------------------------------
#define GS 36

__global__ __launch_bounds__(256, 2)
void gemm_tf32(const float* __restrict__ A, const float* __restrict__ B,
               const float* __restrict__ bias, float* __restrict__ C, int mode)
{
    __shared__ float As[128][GS];
    __shared__ float Bs[128][GS];

    const int tid  = threadIdx.x;
    const int lane = tid & 31, wid = tid >> 5;
    const int g = lane >> 2, t = lane & 3;
    const int wm = (wid >> 1) * 32, wn = (wid & 1) * 64;
    const int m0 = blockIdx.y * 128, n0 = blockIdx.x * 128;

    float acc[2][8][4];
#pragma unroll
    for (int mt = 0; mt < 2; mt++)
#pragma unroll
        for (int nt = 0; nt < 8; nt++)
#pragma unroll
            for (int c = 0; c < 4; c++) acc[mt][nt][c] = 0.f;

    for (int kb = 0; kb < 1024; kb += 32) {
#pragma unroll
        for (int j = 0; j < 4; j++) {
            int l = tid + 256 * j;
            int row = l >> 3, kf = (l & 7) * 4;
            float4 a = *(const float4*)(A + (size_t)(m0 + row) * 1024 + kb + kf);
            float4 bq = *(const float4*)(B + (size_t)(n0 + row) * 1024 + kb + kf);
            float4 ax, bx;
            ax.x = tff(a.x);  ax.y = tff(a.y);  ax.z = tff(a.z);  ax.w = tff(a.w);
            bx.x = tff(bq.x); bx.y = tff(bq.y); bx.z = tff(bq.z); bx.w = tff(bq.w);
            *(float4*)&As[row][kf] = ax;
            *(float4*)&Bs[row][kf] = bx;
        }
        __syncthreads();

#pragma unroll
        for (int kc = 0; kc < 32; kc += 8) {
            unsigned aF[2][4];
#pragma unroll
            for (int mt = 0; mt < 2; mt++) {
                int r = wm + mt * 16 + g;
                aF[mt][0] = __float_as_uint(As[r    ][kc + t]);
                aF[mt][1] = __float_as_uint(As[r + 8][kc + t]);
                aF[mt][2] = __float_as_uint(As[r    ][kc + t + 4]);
                aF[mt][3] = __float_as_uint(As[r + 8][kc + t + 4]);
            }
#pragma unroll
            for (int nt = 0; nt < 8; nt++) {
                int c = wn + nt * 8 + g;
                unsigned b0 = __float_as_uint(Bs[c][kc + t]);
                unsigned b1 = __float_as_uint(Bs[c][kc + t + 4]);
                mma8(acc[0][nt], aF[0], b0, b1);
                mma8(acc[1][nt], aF[1], b0, b1);
            }
        }
        __syncthreads();
    }

#pragma unroll
    for (int nt = 0; nt < 8; nt++) {
        int n = n0 + wn + nt * 8 + 2 * t;
        float bv0 = bias[n], bv1 = bias[n + 1];
#pragma unroll
        for (int mt = 0; mt < 2; mt++) {
            int r = m0 + wm + mt * 16 + g;
            float2 v0 = make_float2(acc[mt][nt][0] + bv0, acc[mt][nt][1] + bv1);
            float2 v1 = make_float2(acc[mt][nt][2] + bv0, acc[mt][nt][3] + bv1);
            if (mode == 0) {
                *(float2*)&C[(size_t)r * 1024 + n]       = v0;
                *(float2*)&C[(size_t)(r + 8) * 1024 + n] = v1;
            } else {
                int h = n >> 6, d = n & 63;
                int bb = r >> 10, tq = r & 1023;
                *(float2*)&C[(size_t)((bb * NH + h) * TT + tq) * DH + d]       = v0;
                *(float2*)&C[(size_t)((bb * NH + h) * TT + tq + 8) * DH + d]   = v1;
            }
        }
    }
}

// ---------------------------------------------------------------------------
// Flash attention, tf32 tensor cores. BLOCK_M=128, BLOCK_N=64, Dh=64.
// 256 thr / 8 warps; warp w owns rows [16w,16w+16) exclusively -> softmax is
// quad-local (shfl xor 1,2). P roundtrips through per-warp smem (__syncwarp).
// All exp in base-2 via FMA-only exp2_fast (no MUFU).
// ---------------------------------------------------------------------------
#define FQ 68   // stride for Qs/Ks/Ps
#define FV 72   // stride for Vs
#define FLASH_SMEM ((128*FQ + 64*FQ + 64*FV + 128*FQ) * 4)   // 105472 B

__global__ __launch_bounds__(256, 2)
void flash_tf32(const float* __restrict__ amask, const unsigned char* __restrict__ kpm)
{
    extern __shared__ float sm[];
    float* Qs = sm;                    // [128][FQ]
    float* Ks = Qs + 128 * FQ;         // [64][FQ]
    float* Vs = Ks + 64 * FQ;          // [64][FV]
    float* Ps = Vs + 64 * FV;          // [128][FQ]

    const int tid  = threadIdx.x;
    const int lane = tid & 31, wid = tid >> 5;
    const int g = lane >> 2, t = lane & 3;
    const int bh = blockIdx.x, b = bh >> 4, h = bh & 15;
    const int m0 = blockIdx.y * 128;

    const float* Qg = g_q + ((size_t)bh * TT + m0) * DH;
    const float* Kg = g_k + (size_t)bh * TT * DH;
    const float* Vg = g_v + (size_t)bh * TT * DH;

    // load Q tile (tf32-rounded)
#pragma unroll
    for (int j = 0; j < 8; j++) {
        int l = tid + 256 * j;
        int row = l >> 4, fc = (l & 15) * 4;
        float4 q = *(const float4*)(Qg + row * 64 + fc);
        float4 qx;
        qx.x = tff(q.x); qx.y = tff(q.y); qx.z = tff(q.z); qx.w = tff(q.w);
        *(float4*)&Qs[row * FQ + fc] = qx;
    }

    float o[8][4];
#pragma unroll
    for (int dt = 0; dt < 8; dt++)
#pragma unroll
        for (int c = 0; c < 4; c++) o[dt][c] = 0.f;

    float mr0 = -1e30f, mr1 = -1e30f, l0 = 0.f, l1 = 0.f;
    const int   r0  = wid * 16 + g;
    const int   tq0 = m0 + r0;
    const float SC2 = 0.125f * LOG2E;

    for (int n0k = 0; n0k < TT; n0k += 64) {
        __syncthreads();   // prior iter done with Ks/Vs
#pragma unroll
        for (int j = 0; j < 4; j++) {
            int l = tid + 256 * j;
            int row = l >> 4, fc = (l & 15) * 4;
            float4 kq = *(const float4*)(Kg + (size_t)(n0k + row) * 64 + fc);
            float4 vq = *(const float4*)(Vg + (size_t)(n0k + row) * 64 + fc);
            float4 kx, vx;
            kx.x = tff(kq.x); kx.y = tff(kq.y); kx.z = tff(kq.z); kx.w = tff(kq.w);
            vx.x = tff(vq.x); vx.y = tff(vq.y); vx.z = tff(vq.z); vx.w = tff(vq.w);
            *(float4*)&Ks[row * FQ + fc] = kx;
            *(float4*)&Vs[row * FV + fc] = vx;
        }
        __syncthreads();

        // ---- S = Q @ K^T ----
        float s[8][4];
#pragma unroll
        for (int nt = 0; nt < 8; nt++)
#pragma unroll
            for (int c = 0; c < 4; c++) s[nt][c] = 0.f;

#pragma unroll
        for (int kc = 0; kc < 64; kc += 8) {
            unsigned aF[4];
            aF[0] = __float_as_uint(Qs[(r0    ) * FQ + kc + t]);
            aF[1] = __float_as_uint(Qs[(r0 + 8) * FQ + kc + t]);
            aF[2] = __float_as_uint(Qs[(r0    ) * FQ + kc + t + 4]);
            aF[3] = __float_as_uint(Qs[(r0 + 8) * FQ + kc + t + 4]);
#pragma unroll
            for (int nt = 0; nt < 8; nt++) {
                unsigned b0 = __float_as_uint(Ks[(nt * 8 + g) * FQ + kc + t]);
                unsigned b1 = __float_as_uint(Ks[(nt * 8 + g) * FQ + kc + t + 4]);
                mma8(s[nt], aF, b0, b1);
            }
        }

        // ---- scale + masks (base-2 domain) ----
#pragma unroll
        for (int nt = 0; nt < 8; nt++) {
            int col = n0k + nt * 8 + 2 * t;
            float2 ma0 = *(const float2*)(amask + (size_t)tq0 * TT + col);
            float2 ma1 = *(const float2*)(amask + (size_t)(tq0 + 8) * TT + col);
            const unsigned char* kp = kpm + b * TT + col;
            float k0 = kp[0] ? -1e30f : 0.f;
            float k1 = kp[1] ? -1e30f : 0.f;
            s[nt][0] = fmaf(s[nt][0], SC2, fmaf(ma0.x, LOG2E, k0));
            s[nt][1] = fmaf(s[nt][1], SC2, fmaf(ma0.y, LOG2E, k1));
            s[nt][2] = fmaf(s[nt][2], SC2, fmaf(ma1.x, LOG2E, k0));
            s[nt][3] = fmaf(s[nt][3], SC2, fmaf(ma1.y, LOG2E, k1));
        }

        // ---- online softmax ----
        float mx0 = -1e30f, mx1 = -1e30f;
#pragma unroll
        for (int nt = 0; nt < 8; nt++) {
            mx0 = fmaxf(mx0, fmaxf(s[nt][0], s[nt][1]));
            mx1 = fmaxf(mx1, fmaxf(s[nt][2], s[nt][3]));
        }
        mx0 = fmaxf(mx0, __shfl_xor_sync(0xffffffffu, mx0, 1));
        mx0 = fmaxf(mx0, __shfl_xor_sync(0xffffffffu, mx0, 2));
        mx1 = fmaxf(mx1, __shfl_xor_sync(0xffffffffu, mx1, 1));
        mx1 = fmaxf(mx1, __shfl_xor_sync(0xffffffffu, mx1, 2));

        float mn0 = fmaxf(mr0, mx0), mn1 = fmaxf(mr1, mx1);
        float al0 = exp2_fast(mr0 - mn0), al1 = exp2_fast(mr1 - mn1);
        mr0 = mn0; mr1 = mn1;

        float rs0 = 0.f, rs1 = 0.f;
#pragma unroll
        for (int nt = 0; nt < 8; nt++) {
            s[nt][0] = exp2_fast(s[nt][0] - mn0);
            s[nt][1] = exp2_fast(s[nt][1] - mn0);
            s[nt][2] = exp2_fast(s[nt][2] - mn1);
            s[nt][3] = exp2_fast(s[nt][3] - mn1);
            rs0 += s[nt][0] + s[nt][1];
            rs1 += s[nt][2] + s[nt][3];
        }
        rs0 += __shfl_xor_sync(0xffffffffu, rs0, 1);
        rs0 += __shfl_xor_sync(0xffffffffu, rs0, 2);
        rs1 += __shfl_xor_sync(0xffffffffu, rs1, 1);
        rs1 += __shfl_xor_sync(0xffffffffu, rs1, 2);
        l0 = l0 * al0 + rs0;
        l1 = l1 * al1 + rs1;

#pragma unroll
        for (int dt = 0; dt < 8; dt++) {
            o[dt][0] *= al0; o[dt][1] *= al0;
            o[dt][2] *= al1; o[dt][3] *= al1;
        }

        // ---- stash P (tf32) into per-warp smem rows ----
#pragma unroll
        for (int nt = 0; nt < 8; nt++) {
            float2 p0 = make_float2(tff(s[nt][0]), tff(s[nt][1]));
            float2 p1 = make_float2(tff(s[nt][2]), tff(s[nt][3]));
            *(float2*)&Ps[(r0    ) * FQ + nt * 8 + 2 * t] = p0;
            *(float2*)&Ps[(r0 + 8) * FQ + nt * 8 + 2 * t] = p1;
        }
        __syncwarp();

        // ---- O += P @ V ----
#pragma unroll
        for (int kc = 0; kc < 64; kc += 8) {
            unsigned aF[4];
            aF[0] = __float_as_uint(Ps[(r0    ) * FQ + kc + t]);
            aF[1] = __float_as_uint(Ps[(r0 + 8) * FQ + kc + t]);
            aF[2] = __float_as_uint(Ps[(r0    ) * FQ + kc + t + 4]);
            aF[3] = __float_as_uint(Ps[(r0 + 8) * FQ + kc + t + 4]);
#pragma unroll
            for (int dt = 0; dt < 8; dt++) {
                unsigned b0 = __float_as_uint(Vs[(kc + t    ) * FV + dt * 8 + g]);
                unsigned b1 = __float_as_uint(Vs[(kc + t + 4) * FV + dt * 8 + g]);
                mma8(o[dt], aF, b0, b1);
            }
        }
    }

    // ---- normalize + write [b, t, h*64+d] ----
    float inv0 = 1.f / l0, inv1 = 1.f / l1;
#pragma unroll
    for (int dt = 0; dt < 8; dt++) {
        int col = h * 64 + dt * 8 + 2 * t;
        float2 v0 = make_float2(o[dt][0] * inv0, o[dt][1] * inv0);
        float2 v1 = make_float2(o[dt][2] * inv1, o[dt][3] * inv1);
        *(float2*)&g_ao[(size_t)(b * TT + tq0    ) * EMB + col] = v0;
        *(float2*)&g_ao[(size_t)(b * TT + tq0 + 8) * EMB + col] = v1;
    }
}

// ============================================================================
extern "C" void kernel_launch(void* const* d_in, const int* in_sizes, int n_in,
                              void* d_out, int out_size)
{
    (void)in_sizes; (void)n_in; (void)out_size;
    const float*         query = (const float*)d_in[0];
    const float*         key   = (const float*)d_in[1];
    const float*         value = (const float*)d_in[2];
    const unsigned char* kpm   = (const unsigned char*)d_in[3];
    const float*         amask = (const float*)d_in[4];
    const float*         win   = (const float*)d_in[5];
    const float*         bin   = (const float*)d_in[6];
    const float*         wout  = (const float*)d_in[7];
    const float*         bout  = (const float*)d_in[8];
    float*               out   = (float*)d_out;

    float *pq, *pk, *pv, *pao;
    cudaGetSymbolAddress((void**)&pq,  g_q);
    cudaGetSymbolAddress((void**)&pk,  g_k);
    cudaGetSymbolAddress((void**)&pv,  g_v);
    cudaGetSymbolAddress((void**)&pao, g_ao);

    dim3 gg(EMB / 128, NTOK / 128);   // (8, 64)

    // Q/K/V projections (scatter into [b,h,t,d])
    gemm_tf32<<<gg, 256>>>(query, win,               bin,        pq, 1);
    gemm_tf32<<<gg, 256>>>(key,   win +   1024*1024, bin + 1024, pk, 1);
    gemm_tf32<<<gg, 256>>>(value, win + 2*1024*1024, bin + 2048, pv, 1);

    // Flash attention
    cudaFuncSetAttribute(flash_tf32,
                         cudaFuncAttributeMaxDynamicSharedMemorySize, FLASH_SMEM);
    flash_tf32<<<dim3(BHD, TT / 128), 256, FLASH_SMEM>>>(amask, kpm);

    // Output projection -> d_out
    gemm_tf32<<<gg, 256>>>(pao, wout, bout, out, 0);
}